// round 1
// baseline (speedup 1.0000x reference)
#include <cuda_runtime.h>
#include <math.h>

#define W 4096
#define S 4096
#define S4 (S/4)          // float4 per row
#define NKMAX 1024
#define SHARP 50.0f

// ---------------- device scratch (no allocations allowed) ----------------
__device__ float2 g_mix[W];     // noisy_mix
__device__ float2 g_tw[W];      // twiddle table e^{i 2pi m / W}
__device__ float  g_corr[NKMAX];
__device__ float  g_attn[NKMAX];
__device__ float2 g_clean[W];   // clean_key

// ---------------- twiddle table: tw[m] = exp(i*2*pi*m/W) ----------------
__global__ void k_table() {
    int i = blockIdx.x * blockDim.x + threadIdx.x;
    if (i < W) {
        float s, c;
        // 2*m/W = m/2048 ; m * 2^-11 is exact in fp32
        sincospif((float)i * (1.0f / 2048.0f), &s, &c);
        g_tw[i] = make_float2(c, s);
    }
}

// ---------------- phase 1: noisy_mix[w] = sum_s holo*conj(cue) ----------------
__global__ __launch_bounds__(256) void k_mix(
    const float4* __restrict__ hr, const float4* __restrict__ hi,
    const float4* __restrict__ cr, const float4* __restrict__ ci)
{
    int row  = blockIdx.x;
    int base = row * S4;
    float re = 0.f, im = 0.f;
#pragma unroll
    for (int k = 0; k < S4 / 256; k++) {
        int i = base + threadIdx.x + k * 256;
        float4 a = hr[i], b = hi[i], c = cr[i], d = ci[i];
        re += a.x * c.x + b.x * d.x;  im += b.x * c.x - a.x * d.x;
        re += a.y * c.y + b.y * d.y;  im += b.y * c.y - a.y * d.y;
        re += a.z * c.z + b.z * d.z;  im += b.z * c.z - a.z * d.z;
        re += a.w * c.w + b.w * d.w;  im += b.w * c.w - a.w * d.w;
    }
#pragma unroll
    for (int off = 16; off; off >>= 1) {
        re += __shfl_xor_sync(0xffffffffu, re, off);
        im += __shfl_xor_sync(0xffffffffu, im, off);
    }
    __shared__ float2 sred[8];
    int wid = threadIdx.x >> 5;
    if ((threadIdx.x & 31) == 0) sred[wid] = make_float2(re, im);
    __syncthreads();
    if (threadIdx.x == 0) {
        float2 acc = sred[0];
#pragma unroll
        for (int i = 1; i < 8; i++) { acc.x += sred[i].x; acc.y += sred[i].y; }
        g_mix[row] = acc;
    }
}

// ---------------- phase 2: correlations[n] = |sum_w keys[n,w]*mix[w]| ----------------
__global__ __launch_bounds__(256) void k_corr(const int* __restrict__ nkp) {
    int n  = blockIdx.x;
    int nk = *nkp;
    if (n >= nk) return;
    __shared__ float2 stw[W];          // 32 KB, twiddle table (scattered access)
    for (int i = threadIdx.x; i < W; i += 256) stw[i] = g_tw[i];
    __syncthreads();

    unsigned f = (unsigned)(n + 1);
    float dre = 0.f, dim = 0.f;
#pragma unroll
    for (int k = 0; k < W / 256; k++) {
        int w = threadIdx.x + k * 256;
        float2 m = g_mix[w];                       // coalesced, L2-hot
        float2 t = stw[(f * (unsigned)w) & (W - 1)];
        dre += t.x * m.x - t.y * m.y;
        dim += t.x * m.y + t.y * m.x;
    }
#pragma unroll
    for (int off = 16; off; off >>= 1) {
        dre += __shfl_xor_sync(0xffffffffu, dre, off);
        dim += __shfl_xor_sync(0xffffffffu, dim, off);
    }
    __shared__ float2 sred[8];
    int wid = threadIdx.x >> 5;
    if ((threadIdx.x & 31) == 0) sred[wid] = make_float2(dre, dim);
    __syncthreads();
    if (threadIdx.x == 0) {
        float2 acc = sred[0];
#pragma unroll
        for (int i = 1; i < 8; i++) { acc.x += sred[i].x; acc.y += sred[i].y; }
        g_corr[n] = sqrtf(acc.x * acc.x + acc.y * acc.y);
    }
}

// ---------------- phase 3: softmax(50*corr) ----------------
__global__ __launch_bounds__(1024) void k_softmax(const int* __restrict__ nkp) {
    int nk = *nkp;
    int t  = threadIdx.x;
    __shared__ float sm[32];
    float l = (t < nk) ? g_corr[t] * SHARP : -INFINITY;

    float v = l;
#pragma unroll
    for (int off = 16; off; off >>= 1) v = fmaxf(v, __shfl_xor_sync(0xffffffffu, v, off));
    if ((t & 31) == 0) sm[t >> 5] = v;
    __syncthreads();
    if (t < 32) {
        float x = sm[t];
#pragma unroll
        for (int off = 16; off; off >>= 1) x = fmaxf(x, __shfl_xor_sync(0xffffffffu, x, off));
        if (t == 0) sm[0] = x;
    }
    __syncthreads();
    float mx = sm[0];
    __syncthreads();

    float e = (t < nk) ? expf(l - mx) : 0.f;
    float s = e;
#pragma unroll
    for (int off = 16; off; off >>= 1) s += __shfl_xor_sync(0xffffffffu, s, off);
    if ((t & 31) == 0) sm[t >> 5] = s;
    __syncthreads();
    if (t < 32) {
        float x = sm[t];
#pragma unroll
        for (int off = 16; off; off >>= 1) x += __shfl_xor_sync(0xffffffffu, x, off);
        if (t == 0) sm[0] = x;
    }
    __syncthreads();
    if (t < NKMAX) g_attn[t] = (t < nk) ? (e / sm[0]) : 0.f;
}

// ---------------- phase 4: clean_key[w] = sum_n attn[n]*keys[n,w] ----------------
// Only keys with attn != 0 contribute (in practice exactly one: the softmax with
// sharpness 50 on correlations ~1e4 is one-hot in fp32). For those keys we
// replicate the reference's fp32 phase arithmetic + accurate sincosf so the
// output matches to ulp-level.
__global__ __launch_bounds__(256) void k_clean(const int* __restrict__ nkp) {
    int w = blockIdx.x * blockDim.x + threadIdx.x;
    if (w >= W) return;
    int nk = *nkp;
    const float F = (float)(6.283185307179586 / 4096.0);  // fl(2*pi/W)
    float fw = (float)w;
    float re = 0.f, im = 0.f;
    for (int n = 0; n < nk; n++) {
        float a = g_attn[n];
        if (a != 0.f) {
            float freq = (float)(n + 1) * F;   // matches reference rounding
            float ph   = freq * fw;            // matches reference rounding
            float s, c;
            sincosf(ph, &s, &c);               // accurate (matches XLA sin/cos)
            re = fmaf(a, c, re);
            im = fmaf(a, s, im);
        }
    }
    g_clean[w] = make_float2(re, im);
}

// ---------------- phase 5: out = holo * clean_key[:,None] ----------------
__global__ __launch_bounds__(256) void k_out(
    const float4* __restrict__ hr, const float4* __restrict__ hi,
    float4* __restrict__ out)
{
    int i = blockIdx.x * blockDim.x + threadIdx.x;   // 0 .. W*S4-1
    int row = i >> 10;                               // / S4
    float2 ck = g_clean[row];
    float4 a = hr[i], b = hi[i];
    float4 o0, o1;
    o0.x = a.x * ck.x - b.x * ck.y;  o1.x = a.x * ck.y + b.x * ck.x;
    o0.y = a.y * ck.x - b.y * ck.y;  o1.y = a.y * ck.y + b.y * ck.x;
    o0.z = a.z * ck.x - b.z * ck.y;  o1.z = a.z * ck.y + b.z * ck.x;
    o0.w = a.w * ck.x - b.w * ck.y;  o1.w = a.w * ck.y + b.w * ck.x;
    out[i]          = o0;            // real plane
    out[i + W * S4] = o1;            // imag plane
}

// ---------------- launcher ----------------
extern "C" void kernel_launch(void* const* d_in, const int* in_sizes, int n_in,
                              void* d_out, int out_size) {
    const float4* hr = (const float4*)d_in[0];
    const float4* hi = (const float4*)d_in[1];
    const float4* cr = (const float4*)d_in[2];
    const float4* ci = (const float4*)d_in[3];
    const int*    nk = (const int*)d_in[4];

    k_table  <<<4, 1024>>>();
    k_mix    <<<W, 256>>>(hr, hi, cr, ci);
    k_corr   <<<NKMAX, 256>>>(nk);
    k_softmax<<<1, 1024>>>(nk);
    k_clean  <<<W / 256, 256>>>(nk);
    k_out    <<<(W * S4) / 256, 256>>>(hr, hi, (float4*)d_out);
}

// round 2
// speedup vs baseline: 1.2918x; 1.2918x over previous
#include <cuda_runtime.h>
#include <math.h>

#define W 4096
#define S 4096
#define S4 (S/4)          // float4 per row
#define NKMAX 1024
#define SHARP 50.0f
#define CKEYS 8           // keys per block in k_corr

// ---------------- device scratch (no allocations allowed) ----------------
__device__ float2 g_mix[W];     // noisy_mix
__device__ float2 g_tw[W];      // twiddle table e^{i 2pi m / W}
__device__ float  g_corr[NKMAX];
__device__ float2 g_clean[W];   // clean_key

// block-wide complex reduction (256 threads, 8 warps)
__device__ __forceinline__ float2 block_reduce_c(float re, float im, float2* sred) {
#pragma unroll
    for (int off = 16; off; off >>= 1) {
        re += __shfl_xor_sync(0xffffffffu, re, off);
        im += __shfl_xor_sync(0xffffffffu, im, off);
    }
    int wid = threadIdx.x >> 5;
    if ((threadIdx.x & 31) == 0) sred[wid] = make_float2(re, im);
    __syncthreads();
    float2 acc = sred[0];
#pragma unroll
    for (int i = 1; i < 8; i++) { acc.x += sred[i].x; acc.y += sred[i].y; }
    return acc;  // valid in all threads (all read same smem)
}

// ---------------- phase 1: noisy_mix[w] = sum_s holo*conj(cue) ----------------
// Side job: blocks 0..15 also fill the twiddle table g_tw (replaces k_table).
__global__ __launch_bounds__(256) void k_mix(
    const float4* __restrict__ hr, const float4* __restrict__ hi,
    const float4* __restrict__ cr, const float4* __restrict__ ci)
{
    int row = blockIdx.x;
    if (row < 16) {
        int i = row * 256 + threadIdx.x;
        float s, c;
        sincospif((float)i * (1.0f / 2048.0f), &s, &c);  // i/2048 exact in fp32
        g_tw[i] = make_float2(c, s);
    }

    int base = row * S4;
    float re = 0.f, im = 0.f;
#pragma unroll
    for (int k = 0; k < S4 / 256; k++) {
        int i = base + threadIdx.x + k * 256;
        float4 a = hr[i];            // keep in L2 (reused by k_out)
        float4 b = hi[i];
        float4 c = __ldcs(&cr[i]);   // streaming: evict-first, spare L2 for hr/hi
        float4 d = __ldcs(&ci[i]);
        re += a.x * c.x + b.x * d.x;  im += b.x * c.x - a.x * d.x;
        re += a.y * c.y + b.y * d.y;  im += b.y * c.y - a.y * d.y;
        re += a.z * c.z + b.z * d.z;  im += b.z * c.z - a.z * d.z;
        re += a.w * c.w + b.w * d.w;  im += b.w * c.w - a.w * d.w;
    }
    __shared__ float2 sred[8];
    float2 acc = block_reduce_c(re, im, sred);
    if (threadIdx.x == 0) g_mix[row] = acc;
}

// ---------------- phase 2: correlations[n] = |sum_w keys[n,w]*mix[w]| ----------------
// 128 blocks x 8 keys; table + mix staged in smem once per block.
__global__ __launch_bounds__(256) void k_corr(const int* __restrict__ nkp) {
    __shared__ float2 stw[W];    // 32 KB
    __shared__ float2 smix[W];   // 32 KB
    __shared__ float2 sred[8];
    int nk = *nkp;
    for (int i = threadIdx.x; i < W; i += 256) { stw[i] = g_tw[i]; smix[i] = g_mix[i]; }
    __syncthreads();

#pragma unroll
    for (int kk = 0; kk < CKEYS; kk++) {
        int n = blockIdx.x * CKEYS + kk;
        if (n >= nk) break;                       // uniform across block
        unsigned f = (unsigned)(n + 1);
        float dre = 0.f, dim = 0.f;
#pragma unroll
        for (int k = 0; k < W / 256; k++) {
            int w = threadIdx.x + k * 256;
            float2 m = smix[w];
            float2 t = stw[(f * (unsigned)w) & (W - 1)];
            dre += t.x * m.x - t.y * m.y;
            dim += t.x * m.y + t.y * m.x;
        }
        float2 acc = block_reduce_c(dre, dim, sred);
        if (threadIdx.x == 0) g_corr[n] = sqrtf(acc.x * acc.x + acc.y * acc.y);
        __syncthreads();                          // sred reuse guard
    }
}

// ---------------- phase 3+4 fused: softmax + clean_key ----------------
// 16 blocks x 256 threads. Each block redundantly computes the softmax over
// 1024 correlations in smem, then its 256 w-positions of clean_key.
// Softmax with sharpness 50 on |corr|~1e4 is one-hot in fp32; for surviving
// keys we replicate the reference's exact fp32 phase arithmetic + sincosf.
__global__ __launch_bounds__(256) void k_clean(const int* __restrict__ nkp) {
    int nk = *nkp;
    int t  = threadIdx.x;
    __shared__ float sattn[NKMAX];
    __shared__ float sredf[8];

    float l[4], mx = -INFINITY;
#pragma unroll
    for (int j = 0; j < 4; j++) {
        int n = t + 256 * j;
        l[j] = (n < nk) ? g_corr[n] * SHARP : -INFINITY;
        mx = fmaxf(mx, l[j]);
    }
    // block max
#pragma unroll
    for (int off = 16; off; off >>= 1) mx = fmaxf(mx, __shfl_xor_sync(0xffffffffu, mx, off));
    if ((t & 31) == 0) sredf[t >> 5] = mx;
    __syncthreads();
    float bm = sredf[0];
#pragma unroll
    for (int i = 1; i < 8; i++) bm = fmaxf(bm, sredf[i]);
    __syncthreads();

    float e[4], s = 0.f;
#pragma unroll
    for (int j = 0; j < 4; j++) {
        int n = t + 256 * j;
        e[j] = (n < nk) ? expf(l[j] - bm) : 0.f;
        s += e[j];
    }
#pragma unroll
    for (int off = 16; off; off >>= 1) s += __shfl_xor_sync(0xffffffffu, s, off);
    if ((t & 31) == 0) sredf[t >> 5] = s;
    __syncthreads();
    float bs = sredf[0];
#pragma unroll
    for (int i = 1; i < 8; i++) bs += sredf[i];

#pragma unroll
    for (int j = 0; j < 4; j++) sattn[t + 256 * j] = e[j] / bs;
    __syncthreads();

    // clean_key for this block's 256 w positions
    int w = blockIdx.x * 256 + t;
    const float F = (float)(6.283185307179586 / 4096.0);  // fl(2*pi/W)
    float fw = (float)w;
    float re = 0.f, im = 0.f;
    for (int n = 0; n < nk; n++) {
        float a = sattn[n];
        if (a != 0.f) {
            float freq = (float)(n + 1) * F;   // reference rounding
            float ph   = freq * fw;            // reference rounding
            float sn, cs;
            sincosf(ph, &sn, &cs);
            re = fmaf(a, cs, re);
            im = fmaf(a, sn, im);
        }
    }
    g_clean[w] = make_float2(re, im);
}

// ---------------- phase 5: out = holo * clean_key[:,None] ----------------
__global__ __launch_bounds__(256) void k_out(
    const float4* __restrict__ hr, const float4* __restrict__ hi,
    float4* __restrict__ out)
{
    int i = blockIdx.x * blockDim.x + threadIdx.x;   // 0 .. W*S4-1
    int row = i >> 10;                               // / S4
    float2 ck = g_clean[row];
    float4 a = hr[i], b = hi[i];                     // partial L2 hits from k_mix
    float4 o0, o1;
    o0.x = a.x * ck.x - b.x * ck.y;  o1.x = a.x * ck.y + b.x * ck.x;
    o0.y = a.y * ck.x - b.y * ck.y;  o1.y = a.y * ck.y + b.y * ck.x;
    o0.z = a.z * ck.x - b.z * ck.y;  o1.z = a.z * ck.y + b.z * ck.x;
    o0.w = a.w * ck.x - b.w * ck.y;  o1.w = a.w * ck.y + b.w * ck.x;
    __stcs(&out[i],          o0);    // real plane (streaming store)
    __stcs(&out[i + W * S4], o1);    // imag plane
}

// ---------------- launcher ----------------
extern "C" void kernel_launch(void* const* d_in, const int* in_sizes, int n_in,
                              void* d_out, int out_size) {
    const float4* hr = (const float4*)d_in[0];
    const float4* hi = (const float4*)d_in[1];
    const float4* cr = (const float4*)d_in[2];
    const float4* ci = (const float4*)d_in[3];
    const int*    nk = (const int*)d_in[4];

    k_mix  <<<W, 256>>>(hr, hi, cr, ci);
    k_corr <<<NKMAX / CKEYS, 256>>>(nk);
    k_clean<<<W / 256, 256>>>(nk);
    k_out  <<<(W * S4) / 256, 256>>>(hr, hi, (float4*)d_out);
}

// round 3
// speedup vs baseline: 1.2941x; 1.0018x over previous
#include <cuda_runtime.h>
#include <math.h>

#define W 4096
#define S 4096
#define S4 (S/4)          // float4 per row
#define NKMAX 1024
#define SHARP 50.0f
#define CKEYS 8           // keys per block in k_corr

// ---------------- device scratch (no allocations allowed) ----------------
__device__ float2 g_mix[W];     // noisy_mix
__device__ float2 g_tw[W];      // twiddle table e^{i 2pi m / W}
__device__ float  g_corr[NKMAX];
__device__ float2 g_clean[W];   // clean_key

// block-wide complex reduction (256 threads, 8 warps)
__device__ __forceinline__ float2 block_reduce_c(float re, float im, float2* sred) {
#pragma unroll
    for (int off = 16; off; off >>= 1) {
        re += __shfl_xor_sync(0xffffffffu, re, off);
        im += __shfl_xor_sync(0xffffffffu, im, off);
    }
    int wid = threadIdx.x >> 5;
    if ((threadIdx.x & 31) == 0) sred[wid] = make_float2(re, im);
    __syncthreads();
    float2 acc = sred[0];
#pragma unroll
    for (int i = 1; i < 8; i++) { acc.x += sred[i].x; acc.y += sred[i].y; }
    return acc;  // valid in all threads (all read same smem)
}

// ---------------- phase 1: noisy_mix[w] = sum_s holo*conj(cue) ----------------
// Side job: blocks 0..15 also fill the twiddle table g_tw (replaces k_table).
__global__ __launch_bounds__(256) void k_mix(
    const float4* __restrict__ hr, const float4* __restrict__ hi,
    const float4* __restrict__ cr, const float4* __restrict__ ci)
{
    int row = blockIdx.x;
    if (row < 16) {
        int i = row * 256 + threadIdx.x;
        float s, c;
        sincospif((float)i * (1.0f / 2048.0f), &s, &c);  // i/2048 exact in fp32
        g_tw[i] = make_float2(c, s);
    }

    int base = row * S4;
    float re = 0.f, im = 0.f;
#pragma unroll
    for (int k = 0; k < S4 / 256; k++) {
        int i = base + threadIdx.x + k * 256;
        float4 a = hr[i];            // keep in L2 (reused by k_out)
        float4 b = hi[i];
        float4 c = __ldcs(&cr[i]);   // streaming: evict-first, spare L2 for hr/hi
        float4 d = __ldcs(&ci[i]);
        re += a.x * c.x + b.x * d.x;  im += b.x * c.x - a.x * d.x;
        re += a.y * c.y + b.y * d.y;  im += b.y * c.y - a.y * d.y;
        re += a.z * c.z + b.z * d.z;  im += b.z * c.z - a.z * d.z;
        re += a.w * c.w + b.w * d.w;  im += b.w * c.w - a.w * d.w;
    }
    __shared__ float2 sred[8];
    float2 acc = block_reduce_c(re, im, sred);
    if (threadIdx.x == 0) g_mix[row] = acc;
}

// ---------------- phase 2: correlations[n] = |sum_w keys[n,w]*mix[w]| ----------------
// 128 blocks x 8 keys; table + mix staged in smem once per block.
__global__ __launch_bounds__(256) void k_corr(const int* __restrict__ nkp) {
    __shared__ float2 stw[W];    // 32 KB
    __shared__ float2 smix[W];   // 32 KB
    __shared__ float2 sred[8];
    int nk = *nkp;
    for (int i = threadIdx.x; i < W; i += 256) { stw[i] = g_tw[i]; smix[i] = g_mix[i]; }
    __syncthreads();

#pragma unroll
    for (int kk = 0; kk < CKEYS; kk++) {
        int n = blockIdx.x * CKEYS + kk;
        if (n >= nk) break;                       // uniform across block
        unsigned f = (unsigned)(n + 1);
        float dre = 0.f, dim = 0.f;
#pragma unroll
        for (int k = 0; k < W / 256; k++) {
            int w = threadIdx.x + k * 256;
            float2 m = smix[w];
            float2 t = stw[(f * (unsigned)w) & (W - 1)];
            dre += t.x * m.x - t.y * m.y;
            dim += t.x * m.y + t.y * m.x;
        }
        float2 acc = block_reduce_c(dre, dim, sred);
        if (threadIdx.x == 0) g_corr[n] = sqrtf(acc.x * acc.x + acc.y * acc.y);
        __syncthreads();                          // sred reuse guard
    }
}

// ---------------- phase 3+4 fused: softmax + clean_key ----------------
// 16 blocks x 256 threads. Each block redundantly computes the softmax over
// 1024 correlations in smem, then its 256 w-positions of clean_key.
// Softmax with sharpness 50 on |corr|~1e4 is one-hot in fp32; for surviving
// keys we replicate the reference's exact fp32 phase arithmetic + sincosf.
__global__ __launch_bounds__(256) void k_clean(const int* __restrict__ nkp) {
    int nk = *nkp;
    int t  = threadIdx.x;
    __shared__ float sattn[NKMAX];
    __shared__ float sredf[8];

    float l[4], mx = -INFINITY;
#pragma unroll
    for (int j = 0; j < 4; j++) {
        int n = t + 256 * j;
        l[j] = (n < nk) ? g_corr[n] * SHARP : -INFINITY;
        mx = fmaxf(mx, l[j]);
    }
    // block max
#pragma unroll
    for (int off = 16; off; off >>= 1) mx = fmaxf(mx, __shfl_xor_sync(0xffffffffu, mx, off));
    if ((t & 31) == 0) sredf[t >> 5] = mx;
    __syncthreads();
    float bm = sredf[0];
#pragma unroll
    for (int i = 1; i < 8; i++) bm = fmaxf(bm, sredf[i]);
    __syncthreads();

    float e[4], s = 0.f;
#pragma unroll
    for (int j = 0; j < 4; j++) {
        int n = t + 256 * j;
        e[j] = (n < nk) ? expf(l[j] - bm) : 0.f;
        s += e[j];
    }
#pragma unroll
    for (int off = 16; off; off >>= 1) s += __shfl_xor_sync(0xffffffffu, s, off);
    if ((t & 31) == 0) sredf[t >> 5] = s;
    __syncthreads();
    float bs = sredf[0];
#pragma unroll
    for (int i = 1; i < 8; i++) bs += sredf[i];

#pragma unroll
    for (int j = 0; j < 4; j++) sattn[t + 256 * j] = e[j] / bs;
    __syncthreads();

    // clean_key for this block's 256 w positions
    int w = blockIdx.x * 256 + t;
    const float F = (float)(6.283185307179586 / 4096.0);  // fl(2*pi/W)
    float fw = (float)w;
    float re = 0.f, im = 0.f;
    for (int n = 0; n < nk; n++) {
        float a = sattn[n];
        if (a != 0.f) {
            float freq = (float)(n + 1) * F;   // reference rounding
            float ph   = freq * fw;            // reference rounding
            float sn, cs;
            sincosf(ph, &sn, &cs);
            re = fmaf(a, cs, re);
            im = fmaf(a, sn, im);
        }
    }
    g_clean[w] = make_float2(re, im);
}

// ---------------- phase 5: out = holo * clean_key[:,None] ----------------
__global__ __launch_bounds__(256) void k_out(
    const float4* __restrict__ hr, const float4* __restrict__ hi,
    float4* __restrict__ out)
{
    int i = blockIdx.x * blockDim.x + threadIdx.x;   // 0 .. W*S4-1
    int row = i >> 10;                               // / S4
    float2 ck = g_clean[row];
    float4 a = hr[i], b = hi[i];                     // partial L2 hits from k_mix
    float4 o0, o1;
    o0.x = a.x * ck.x - b.x * ck.y;  o1.x = a.x * ck.y + b.x * ck.x;
    o0.y = a.y * ck.x - b.y * ck.y;  o1.y = a.y * ck.y + b.y * ck.x;
    o0.z = a.z * ck.x - b.z * ck.y;  o1.z = a.z * ck.y + b.z * ck.x;
    o0.w = a.w * ck.x - b.w * ck.y;  o1.w = a.w * ck.y + b.w * ck.x;
    __stcs(&out[i],          o0);    // real plane (streaming store)
    __stcs(&out[i + W * S4], o1);    // imag plane
}

// ---------------- launcher ----------------
extern "C" void kernel_launch(void* const* d_in, const int* in_sizes, int n_in,
                              void* d_out, int out_size) {
    const float4* hr = (const float4*)d_in[0];
    const float4* hi = (const float4*)d_in[1];
    const float4* cr = (const float4*)d_in[2];
    const float4* ci = (const float4*)d_in[3];
    const int*    nk = (const int*)d_in[4];

    k_mix  <<<W, 256>>>(hr, hi, cr, ci);
    k_corr <<<NKMAX / CKEYS, 256>>>(nk);
    k_clean<<<W / 256, 256>>>(nk);
    k_out  <<<(W * S4) / 256, 256>>>(hr, hi, (float4*)d_out);
}

// round 4
// speedup vs baseline: 1.8549x; 1.4334x over previous
#include <cuda_runtime.h>
#include <math.h>

#define W 4096
#define S 4096
#define S4 (S/4)          // float4 per row
#define NKMAX 1024
#define SHARP 50.0f
#define CKEYS 8           // keys per block in k_corr
#define MAXWIN 64

// ---------------- device scratch (no allocations allowed) ----------------
__device__ float2 g_mix[W];       // noisy_mix
__device__ float2 g_tw[W];        // twiddle table e^{i 2pi m / W}
__device__ float  g_corr[NKMAX];
__device__ unsigned g_done;       // k_corr completion counter (reset by k_mix)
__device__ int    g_nwin;         // number of nonzero-attention winners
__device__ int    g_winn[MAXWIN]; // winner key indices (sorted ascending)
__device__ float  g_wina[MAXWIN]; // winner attention weights

// block-wide complex reduction (256 threads, 8 warps)
__device__ __forceinline__ float2 block_reduce_c(float re, float im, float2* sred) {
#pragma unroll
    for (int off = 16; off; off >>= 1) {
        re += __shfl_xor_sync(0xffffffffu, re, off);
        im += __shfl_xor_sync(0xffffffffu, im, off);
    }
    int wid = threadIdx.x >> 5;
    if ((threadIdx.x & 31) == 0) sred[wid] = make_float2(re, im);
    __syncthreads();
    float2 acc = sred[0];
#pragma unroll
    for (int i = 1; i < 8; i++) { acc.x += sred[i].x; acc.y += sred[i].y; }
    return acc;
}

// ---------------- phase 1: noisy_mix[w] = sum_s holo*conj(cue) ----------------
// Side jobs: blocks 0..15 fill the twiddle table; block 0 resets g_done.
__global__ __launch_bounds__(256) void k_mix(
    const float4* __restrict__ hr, const float4* __restrict__ hi,
    const float4* __restrict__ cr, const float4* __restrict__ ci)
{
    int row = blockIdx.x;
    if (row == 0 && threadIdx.x == 0) g_done = 0u;
    if (row < 16) {
        int i = row * 256 + threadIdx.x;
        float s, c;
        sincospif((float)i * (1.0f / 2048.0f), &s, &c);  // i/2048 exact in fp32
        g_tw[i] = make_float2(c, s);
    }

    int base = row * S4;
    float re = 0.f, im = 0.f;
#pragma unroll
    for (int k = 0; k < S4 / 256; k++) {
        int i = base + threadIdx.x + k * 256;
        float4 a = hr[i];            // default policy: retain in L2 for k_out
        float4 b = hi[i];
        float4 c = __ldcs(&cr[i]);   // streaming: don't evict hr/hi
        float4 d = __ldcs(&ci[i]);
        re += a.x * c.x + b.x * d.x;  im += b.x * c.x - a.x * d.x;
        re += a.y * c.y + b.y * d.y;  im += b.y * c.y - a.y * d.y;
        re += a.z * c.z + b.z * d.z;  im += b.z * c.z - a.z * d.z;
        re += a.w * c.w + b.w * d.w;  im += b.w * c.w - a.w * d.w;
    }
    __shared__ float2 sred[8];
    float2 acc = block_reduce_c(re, im, sred);
    if (threadIdx.x == 0) g_mix[row] = acc;
}

// ---------------- phase 2: correlations + (last block) softmax/compaction ----
__global__ __launch_bounds__(256) void k_corr(const int* __restrict__ nkp) {
    __shared__ float2 stw[W];    // 32 KB
    __shared__ float2 smix[W];   // 32 KB
    __shared__ float2 sred[8];
    int nk = *nkp;
    for (int i = threadIdx.x; i < W; i += 256) { stw[i] = g_tw[i]; smix[i] = g_mix[i]; }
    __syncthreads();

#pragma unroll
    for (int kk = 0; kk < CKEYS; kk++) {
        int n = blockIdx.x * CKEYS + kk;
        if (n >= nk) break;
        unsigned f = (unsigned)(n + 1);
        float dre = 0.f, dim = 0.f;
#pragma unroll
        for (int k = 0; k < W / 256; k++) {
            int w = threadIdx.x + k * 256;
            float2 m = smix[w];
            float2 t = stw[(f * (unsigned)w) & (W - 1)];
            dre += t.x * m.x - t.y * m.y;
            dim += t.x * m.y + t.y * m.x;
        }
        float2 acc = block_reduce_c(dre, dim, sred);
        if (threadIdx.x == 0) g_corr[n] = sqrtf(acc.x * acc.x + acc.y * acc.y);
        __syncthreads();
    }

    // ---- last-arriving block does softmax + winner compaction ----
    __shared__ bool s_last;
    __threadfence();
    if (threadIdx.x == 0)
        s_last = (atomicAdd(&g_done, 1u) == (unsigned)(gridDim.x - 1));
    __syncthreads();
    if (!s_last) return;

    int t = threadIdx.x;
    __shared__ float sredf[8];
    __shared__ float slog[NKMAX];
    __shared__ int   s_cnt;
    if (t == 0) s_cnt = 0;

    float l[4], mx = -INFINITY;
#pragma unroll
    for (int j = 0; j < 4; j++) {
        int n = t + 256 * j;
        float c = (n < nk) ? __ldcg(&g_corr[n]) : 0.f;
        l[j] = (n < nk) ? c * SHARP : -INFINITY;
        mx = fmaxf(mx, l[j]);
    }
#pragma unroll
    for (int off = 16; off; off >>= 1) mx = fmaxf(mx, __shfl_xor_sync(0xffffffffu, mx, off));
    if ((t & 31) == 0) sredf[t >> 5] = mx;
    __syncthreads();
    float bm = sredf[0];
#pragma unroll
    for (int i = 1; i < 8; i++) bm = fmaxf(bm, sredf[i]);
    __syncthreads();

    float e[4], s = 0.f;
#pragma unroll
    for (int j = 0; j < 4; j++) {
        int n = t + 256 * j;
        e[j] = (n < nk) ? expf(l[j] - bm) : 0.f;
        slog[t + 256 * j] = e[j];
        s += e[j];
    }
#pragma unroll
    for (int off = 16; off; off >>= 1) s += __shfl_xor_sync(0xffffffffu, s, off);
    if ((t & 31) == 0) sredf[t >> 5] = s;
    __syncthreads();
    float bs = sredf[0];
#pragma unroll
    for (int i = 1; i < 8; i++) bs += sredf[i];
    __syncthreads();

    // compact nonzero attention entries
#pragma unroll
    for (int j = 0; j < 4; j++) {
        int n = t + 256 * j;
        float a = slog[n] / bs;
        if (a != 0.f && n < nk) {
            int slot = atomicAdd(&s_cnt, 1);
            if (slot < MAXWIN) { g_winn[slot] = n; g_wina[slot] = a; }
        }
    }
    __syncthreads();
    if (t == 0) {
        int m = s_cnt < MAXWIN ? s_cnt : MAXWIN;
        // insertion sort ascending by n (reference's fp32 summation order)
        for (int i = 1; i < m; i++) {
            int   kn = g_winn[i];
            float ka = g_wina[i];
            int j = i - 1;
            while (j >= 0 && g_winn[j] > kn) {
                g_winn[j + 1] = g_winn[j]; g_wina[j + 1] = g_wina[j]; j--;
            }
            g_winn[j + 1] = kn; g_wina[j + 1] = ka;
        }
        g_nwin = m;
    }
}

// ---------------- phase 3: out = holo * clean_key[:,None] ----------------
// One row per block, processed in REVERSE row order so the first reads hit the
// L2-hot tail left by k_mix. clean[row] computed inline from winner list.
__global__ __launch_bounds__(256) void k_out(
    const float4* __restrict__ hr, const float4* __restrict__ hi,
    float4* __restrict__ out)
{
    int row = (W - 1) - blockIdx.x;        // reverse order
    // compute clean[row] (redundantly per thread; m is ~1)
    int m = g_nwin;
    const float F = (float)(6.283185307179586 / 4096.0);  // fl(2*pi/W)
    float fw = (float)row;
    float ckre = 0.f, ckim = 0.f;
    for (int i = 0; i < m; i++) {
        int   n = g_winn[i];
        float a = g_wina[i];
        float freq = (float)(n + 1) * F;   // reference rounding
        float ph   = freq * fw;            // reference rounding
        float sn, cs;
        sincosf(ph, &sn, &cs);
        ckre = fmaf(a, cs, ckre);
        ckim = fmaf(a, sn, ckim);
    }

    int base = row * S4;
#pragma unroll
    for (int k = 0; k < S4 / 256; k++) {
        int i = base + threadIdx.x + k * 256;
        float4 a = __ldcs(&hr[i]);         // consume-once: evict-first
        float4 b = __ldcs(&hi[i]);
        float4 o0, o1;
        o0.x = a.x * ckre - b.x * ckim;  o1.x = a.x * ckim + b.x * ckre;
        o0.y = a.y * ckre - b.y * ckim;  o1.y = a.y * ckim + b.y * ckre;
        o0.z = a.z * ckre - b.z * ckim;  o1.z = a.z * ckim + b.z * ckre;
        o0.w = a.w * ckre - b.w * ckim;  o1.w = a.w * ckim + b.w * ckre;
        __stcs(&out[i],          o0);      // real plane
        __stcs(&out[i + W * S4], o1);      // imag plane
    }
}

// ---------------- launcher ----------------
extern "C" void kernel_launch(void* const* d_in, const int* in_sizes, int n_in,
                              void* d_out, int out_size) {
    const float4* hr = (const float4*)d_in[0];
    const float4* hi = (const float4*)d_in[1];
    const float4* cr = (const float4*)d_in[2];
    const float4* ci = (const float4*)d_in[3];
    const int*    nk = (const int*)d_in[4];

    k_mix  <<<W, 256>>>(hr, hi, cr, ci);
    k_corr <<<NKMAX / CKEYS, 256>>>(nk);
    k_out  <<<W, 256>>>(hr, hi, (float4*)d_out);
}

// round 5
// speedup vs baseline: 1.8722x; 1.0093x over previous
#include <cuda_runtime.h>
#include <math.h>

#define W 4096
#define S 4096
#define S4 (S/4)          // float4 per row
#define NKMAX 1024
#define SHARP 50.0f
#define CKEYS 8           // keys per block in k_corr
#define MAXWIN 64

// ---------------- device scratch (no allocations allowed) ----------------
__device__ float2 g_mix[W];       // noisy_mix
__device__ float2 g_tw[W];        // twiddle table e^{i 2pi m / W}
__device__ float  g_corr[NKMAX];
__device__ unsigned g_done;       // k_corr completion counter (reset by k_mix)
__device__ int    g_nwin;         // number of nonzero-attention winners
__device__ int    g_winn[MAXWIN]; // winner key indices (sorted ascending)
__device__ float  g_wina[MAXWIN]; // winner attention weights

// block-wide complex reduction (256 threads, 8 warps)
__device__ __forceinline__ float2 block_reduce_c(float re, float im, float2* sred) {
#pragma unroll
    for (int off = 16; off; off >>= 1) {
        re += __shfl_xor_sync(0xffffffffu, re, off);
        im += __shfl_xor_sync(0xffffffffu, im, off);
    }
    int wid = threadIdx.x >> 5;
    if ((threadIdx.x & 31) == 0) sred[wid] = make_float2(re, im);
    __syncthreads();
    float2 acc = sred[0];
#pragma unroll
    for (int i = 1; i < 8; i++) { acc.x += sred[i].x; acc.y += sred[i].y; }
    return acc;
}

// ---------------- phase 1: noisy_mix[w] = sum_s holo*conj(cue) ----------------
// Side jobs: blocks 0..15 fill the twiddle table; block 0 resets g_done.
__global__ __launch_bounds__(256) void k_mix(
    const float4* __restrict__ hr, const float4* __restrict__ hi,
    const float4* __restrict__ cr, const float4* __restrict__ ci)
{
    int row = blockIdx.x;
    if (row == 0 && threadIdx.x == 0) g_done = 0u;
    if (row < 16) {
        int i = row * 256 + threadIdx.x;
        float s, c;
        sincospif((float)i * (1.0f / 2048.0f), &s, &c);  // i/2048 exact in fp32
        g_tw[i] = make_float2(c, s);
    }

    int base = row * S4;
    float re = 0.f, im = 0.f;
#pragma unroll
    for (int k = 0; k < S4 / 256; k++) {
        int i = base + threadIdx.x + k * 256;
        float4 a = hr[i];            // default policy: retain in L2 for k_out
        float4 b = hi[i];
        float4 c = __ldcs(&cr[i]);   // streaming: don't evict hr/hi
        float4 d = __ldcs(&ci[i]);
        re += a.x * c.x + b.x * d.x;  im += b.x * c.x - a.x * d.x;
        re += a.y * c.y + b.y * d.y;  im += b.y * c.y - a.y * d.y;
        re += a.z * c.z + b.z * d.z;  im += b.z * c.z - a.z * d.z;
        re += a.w * c.w + b.w * d.w;  im += b.w * c.w - a.w * d.w;
    }
    __shared__ float2 sred[8];
    float2 acc = block_reduce_c(re, im, sred);
    if (threadIdx.x == 0) g_mix[row] = acc;
}

// ---------------- phase 2: correlations + (last block) softmax/compaction ----
__global__ __launch_bounds__(256) void k_corr(const int* __restrict__ nkp) {
    __shared__ float2 stw[W];    // 32 KB
    __shared__ float2 smix[W];   // 32 KB
    __shared__ float2 sred[8];
    int nk = *nkp;
    for (int i = threadIdx.x; i < W; i += 256) { stw[i] = g_tw[i]; smix[i] = g_mix[i]; }
    __syncthreads();

#pragma unroll
    for (int kk = 0; kk < CKEYS; kk++) {
        int n = blockIdx.x * CKEYS + kk;
        if (n >= nk) break;
        unsigned f = (unsigned)(n + 1);
        float dre = 0.f, dim = 0.f;
#pragma unroll
        for (int k = 0; k < W / 256; k++) {
            int w = threadIdx.x + k * 256;
            float2 m = smix[w];
            float2 t = stw[(f * (unsigned)w) & (W - 1)];
            dre += t.x * m.x - t.y * m.y;
            dim += t.x * m.y + t.y * m.x;
        }
        float2 acc = block_reduce_c(dre, dim, sred);
        if (threadIdx.x == 0) g_corr[n] = sqrtf(acc.x * acc.x + acc.y * acc.y);
        __syncthreads();
    }

    // ---- last-arriving block does softmax + winner compaction ----
    __shared__ bool s_last;
    __threadfence();
    if (threadIdx.x == 0)
        s_last = (atomicAdd(&g_done, 1u) == (unsigned)(gridDim.x - 1));
    __syncthreads();
    if (!s_last) return;

    int t = threadIdx.x;
    __shared__ float sredf[8];
    __shared__ float slog[NKMAX];
    __shared__ int   s_cnt;
    if (t == 0) s_cnt = 0;

    float l[4], mx = -INFINITY;
#pragma unroll
    for (int j = 0; j < 4; j++) {
        int n = t + 256 * j;
        float c = (n < nk) ? __ldcg(&g_corr[n]) : 0.f;
        l[j] = (n < nk) ? c * SHARP : -INFINITY;
        mx = fmaxf(mx, l[j]);
    }
#pragma unroll
    for (int off = 16; off; off >>= 1) mx = fmaxf(mx, __shfl_xor_sync(0xffffffffu, mx, off));
    if ((t & 31) == 0) sredf[t >> 5] = mx;
    __syncthreads();
    float bm = sredf[0];
#pragma unroll
    for (int i = 1; i < 8; i++) bm = fmaxf(bm, sredf[i]);
    __syncthreads();

    float e[4], s = 0.f;
#pragma unroll
    for (int j = 0; j < 4; j++) {
        int n = t + 256 * j;
        e[j] = (n < nk) ? expf(l[j] - bm) : 0.f;
        slog[t + 256 * j] = e[j];
        s += e[j];
    }
#pragma unroll
    for (int off = 16; off; off >>= 1) s += __shfl_xor_sync(0xffffffffu, s, off);
    if ((t & 31) == 0) sredf[t >> 5] = s;
    __syncthreads();
    float bs = sredf[0];
#pragma unroll
    for (int i = 1; i < 8; i++) bs += sredf[i];
    __syncthreads();

    // compact nonzero attention entries
#pragma unroll
    for (int j = 0; j < 4; j++) {
        int n = t + 256 * j;
        float a = slog[n] / bs;
        if (a != 0.f && n < nk) {
            int slot = atomicAdd(&s_cnt, 1);
            if (slot < MAXWIN) { g_winn[slot] = n; g_wina[slot] = a; }
        }
    }
    __syncthreads();
    if (t == 0) {
        int m = s_cnt < MAXWIN ? s_cnt : MAXWIN;
        // insertion sort ascending by n (reference's fp32 summation order)
        for (int i = 1; i < m; i++) {
            int   kn = g_winn[i];
            float ka = g_wina[i];
            int j = i - 1;
            while (j >= 0 && g_winn[j] > kn) {
                g_winn[j + 1] = g_winn[j]; g_wina[j + 1] = g_wina[j]; j--;
            }
            g_winn[j + 1] = kn; g_wina[j + 1] = ka;
        }
        g_nwin = m;
    }
}

// ---------------- phase 3: out = holo * clean_key[:,None] ----------------
// One row per block, processed in REVERSE row order so the first reads hit the
// L2-hot tail left by k_mix. clean[row] computed inline from winner list.
__global__ __launch_bounds__(256) void k_out(
    const float4* __restrict__ hr, const float4* __restrict__ hi,
    float4* __restrict__ out)
{
    int row = (W - 1) - blockIdx.x;        // reverse order
    // compute clean[row] (redundantly per thread; m is ~1)
    int m = g_nwin;
    const float F = (float)(6.283185307179586 / 4096.0);  // fl(2*pi/W)
    float fw = (float)row;
    float ckre = 0.f, ckim = 0.f;
    for (int i = 0; i < m; i++) {
        int   n = g_winn[i];
        float a = g_wina[i];
        float freq = (float)(n + 1) * F;   // reference rounding
        float ph   = freq * fw;            // reference rounding
        float sn, cs;
        sincosf(ph, &sn, &cs);
        ckre = fmaf(a, cs, ckre);
        ckim = fmaf(a, sn, ckim);
    }

    int base = row * S4;
#pragma unroll
    for (int k = 0; k < S4 / 256; k++) {
        int i = base + threadIdx.x + k * 256;
        float4 a = __ldcs(&hr[i]);         // consume-once: evict-first
        float4 b = __ldcs(&hi[i]);
        float4 o0, o1;
        o0.x = a.x * ckre - b.x * ckim;  o1.x = a.x * ckim + b.x * ckre;
        o0.y = a.y * ckre - b.y * ckim;  o1.y = a.y * ckim + b.y * ckre;
        o0.z = a.z * ckre - b.z * ckim;  o1.z = a.z * ckim + b.z * ckre;
        o0.w = a.w * ckre - b.w * ckim;  o1.w = a.w * ckim + b.w * ckre;
        __stcs(&out[i],          o0);      // real plane
        __stcs(&out[i + W * S4], o1);      // imag plane
    }
}

// ---------------- launcher ----------------
extern "C" void kernel_launch(void* const* d_in, const int* in_sizes, int n_in,
                              void* d_out, int out_size) {
    const float4* hr = (const float4*)d_in[0];
    const float4* hi = (const float4*)d_in[1];
    const float4* cr = (const float4*)d_in[2];
    const float4* ci = (const float4*)d_in[3];
    const int*    nk = (const int*)d_in[4];

    k_mix  <<<W, 256>>>(hr, hi, cr, ci);
    k_corr <<<NKMAX / CKEYS, 256>>>(nk);
    k_out  <<<W, 256>>>(hr, hi, (float4*)d_out);
}

// round 6
// speedup vs baseline: 1.8813x; 1.0049x over previous
#include <cuda_runtime.h>
#include <math.h>

#define W 4096
#define S 4096
#define S4 (S/4)          // float4 per row
#define NKMAX 1024
#define SHARP 50.0f
#define MAXWIN 64
#define CBLK 256          // number of ticket-selected correlation blocks
#define CK   (NKMAX/CBLK) // keys per correlation block (4)

// ---------------- device scratch (no allocations allowed) ----------------
__device__ float2 g_mix[W];       // noisy_mix
__device__ float2 g_tw[W];        // twiddle table e^{i 2pi m / W}
__device__ float  g_corr[NKMAX];
__device__ unsigned g_t1;         // mix ticket counter  (monotonic across replays)
__device__ unsigned g_t2;         // corr ticket counter (monotonic across replays)
__device__ int    g_nwin;         // number of nonzero-attention winners
__device__ int    g_winn[MAXWIN]; // winner key indices (sorted ascending)
__device__ float  g_wina[MAXWIN]; // winner attention weights

// block-wide complex reduction (256 threads, 8 warps). Caller syncs before reuse.
__device__ __forceinline__ float2 block_reduce_c(float re, float im, float2* sred) {
#pragma unroll
    for (int off = 16; off; off >>= 1) {
        re += __shfl_xor_sync(0xffffffffu, re, off);
        im += __shfl_xor_sync(0xffffffffu, im, off);
    }
    int wid = threadIdx.x >> 5;
    if ((threadIdx.x & 31) == 0) sred[wid] = make_float2(re, im);
    __syncthreads();
    float2 acc = sred[0];
#pragma unroll
    for (int i = 1; i < 8; i++) { acc.x += sred[i].x; acc.y += sred[i].y; }
    return acc;
}

// ============ fused: mix + (last 256 blocks) correlations + (last) softmax ====
__global__ __launch_bounds__(256, 6) void k_main(
    const float4* __restrict__ hr, const float4* __restrict__ hi,
    const float4* __restrict__ cr, const float4* __restrict__ ci,
    const int* __restrict__ nkp)
{
    int row = blockIdx.x;
    int t   = threadIdx.x;
    __shared__ float2 sred[8];

    // side job: blocks 0..15 fill the twiddle table
    if (row < 16) {
        int i = row * 256 + t;
        float s, c;
        sincospif((float)i * (1.0f / 2048.0f), &s, &c);  // i/2048 exact in fp32
        g_tw[i] = make_float2(c, s);
    }

    // ---- phase 1: noisy_mix row ----
    {
        int base = row * S4;
        float re = 0.f, im = 0.f;
#pragma unroll
        for (int k = 0; k < S4 / 256; k++) {
            int i = base + t + k * 256;
            float4 a = hr[i];            // retain in L2 for k_out
            float4 b = hi[i];
            float4 c = __ldcs(&cr[i]);   // streaming
            float4 d = __ldcs(&ci[i]);
            re += a.x * c.x + b.x * d.x;  im += b.x * c.x - a.x * d.x;
            re += a.y * c.y + b.y * d.y;  im += b.y * c.y - a.y * d.y;
            re += a.z * c.z + b.z * d.z;  im += b.z * c.z - a.z * d.z;
            re += a.w * c.w + b.w * d.w;  im += b.w * c.w - a.w * d.w;
        }
        float2 acc = block_reduce_c(re, im, sred);
        if (t == 0) g_mix[row] = acc;
    }
    __threadfence();

    // ---- ticket: last CBLK finishers become correlation blocks ----
    __shared__ unsigned sT;
    if (t == 0) sT = atomicAdd(&g_t1, 1u);
    __syncthreads();
    unsigned T = sT;
    unsigned target = ((T >> 12) + 1u) << 12;   // next multiple of 4096
    if (T < target - CBLK) return;
    unsigned cid = T - (target - CBLK);         // 0..CBLK-1

    if (t == 0) {  // wait until all 4096 rows of this replay are committed
        volatile unsigned* p = &g_t1;
        while (*p < target) __nanosleep(32);
    }
    __syncthreads();
    __threadfence();

    int nk = *nkp;

    // ---- phase 2: correlations for CK keys via register phasor recurrence ----
    // key f: twiddle at w advances by rot = e^{i 2pi f*256/W} per 256-step chunk
    float tre[CK], tim[CK], rre[CK], rim[CK], are[CK], aim[CK];
#pragma unroll
    for (int kk = 0; kk < CK; kk++) {
        unsigned f = (unsigned)(cid * CK + kk) + 1u;
        float2 t0 = g_tw[(f * (unsigned)t) & 4095u];   // exact init
        float2 r0 = g_tw[(f << 8) & 4095u];            // exact rotation const
        tre[kk] = t0.x; tim[kk] = t0.y;
        rre[kk] = r0.x; rim[kk] = r0.y;
        are[kk] = 0.f;  aim[kk] = 0.f;
    }
#pragma unroll
    for (int ch = 0; ch < W / 256; ch++) {
        float2 m = __ldg(&g_mix[t + 256 * ch]);        // L2-hot, coalesced
#pragma unroll
        for (int kk = 0; kk < CK; kk++) {
            are[kk] += tre[kk] * m.x - tim[kk] * m.y;
            aim[kk] += tre[kk] * m.y + tim[kk] * m.x;
            float nr = tre[kk] * rre[kk] - tim[kk] * rim[kk];
            tim[kk]  = tre[kk] * rim[kk] + tim[kk] * rre[kk];
            tre[kk]  = nr;
        }
    }
#pragma unroll
    for (int kk = 0; kk < CK; kk++) {
        float2 acc = block_reduce_c(are[kk], aim[kk], sred);
        int n = cid * CK + kk;
        if (t == 0 && n < nk) g_corr[n] = sqrtf(acc.x * acc.x + acc.y * acc.y);
        __syncthreads();   // sred reuse guard
    }
    __threadfence();

    // ---- corr ticket: last of the CBLK blocks does softmax + compaction ----
    __shared__ unsigned sT2;
    if (t == 0) sT2 = atomicAdd(&g_t2, 1u);
    __syncthreads();
    if ((sT2 & (CBLK - 1u)) != (CBLK - 1u)) return;

    // softmax over nk correlations (one-hot in practice); compact winners
    __shared__ float sredf[8];
    __shared__ float slog[NKMAX];
    __shared__ int   s_cnt;
    if (t == 0) s_cnt = 0;

    float l[4], mx = -INFINITY;
#pragma unroll
    for (int j = 0; j < 4; j++) {
        int n = t + 256 * j;
        float c = (n < nk) ? __ldcg(&g_corr[n]) : 0.f;
        l[j] = (n < nk) ? c * SHARP : -INFINITY;
        mx = fmaxf(mx, l[j]);
    }
#pragma unroll
    for (int off = 16; off; off >>= 1) mx = fmaxf(mx, __shfl_xor_sync(0xffffffffu, mx, off));
    if ((t & 31) == 0) sredf[t >> 5] = mx;
    __syncthreads();
    float bm = sredf[0];
#pragma unroll
    for (int i = 1; i < 8; i++) bm = fmaxf(bm, sredf[i]);
    __syncthreads();

    float e[4], s = 0.f;
#pragma unroll
    for (int j = 0; j < 4; j++) {
        int n = t + 256 * j;
        e[j] = (n < nk) ? expf(l[j] - bm) : 0.f;
        slog[t + 256 * j] = e[j];
        s += e[j];
    }
#pragma unroll
    for (int off = 16; off; off >>= 1) s += __shfl_xor_sync(0xffffffffu, s, off);
    if ((t & 31) == 0) sredf[t >> 5] = s;
    __syncthreads();
    float bs = sredf[0];
#pragma unroll
    for (int i = 1; i < 8; i++) bs += sredf[i];
    __syncthreads();

#pragma unroll
    for (int j = 0; j < 4; j++) {
        int n = t + 256 * j;
        float a = slog[n] / bs;
        if (a != 0.f && n < nk) {
            int slot = atomicAdd(&s_cnt, 1);
            if (slot < MAXWIN) { g_winn[slot] = n; g_wina[slot] = a; }
        }
    }
    __syncthreads();
    if (t == 0) {
        int m = s_cnt < MAXWIN ? s_cnt : MAXWIN;
        for (int i = 1; i < m; i++) {           // sort ascending by n
            int   kn = g_winn[i];
            float ka = g_wina[i];
            int j = i - 1;
            while (j >= 0 && g_winn[j] > kn) {
                g_winn[j + 1] = g_winn[j]; g_wina[j + 1] = g_wina[j]; j--;
            }
            g_winn[j + 1] = kn; g_wina[j + 1] = ka;
        }
        g_nwin = m;
    }
}

// ---------------- phase 3: out = holo * clean_key[:,None] ----------------
// One row per block, REVERSE order so first reads hit the L2-hot tail of k_main.
__global__ __launch_bounds__(256) void k_out(
    const float4* __restrict__ hr, const float4* __restrict__ hi,
    float4* __restrict__ out)
{
    int row = (W - 1) - blockIdx.x;
    int m = g_nwin;
    const float F = (float)(6.283185307179586 / 4096.0);  // fl(2*pi/W)
    float fw = (float)row;
    float ckre = 0.f, ckim = 0.f;
    for (int i = 0; i < m; i++) {
        int   n = g_winn[i];
        float a = g_wina[i];
        float freq = (float)(n + 1) * F;   // reference rounding order
        float ph   = freq * fw;
        float sn, cs;
        sincosf(ph, &sn, &cs);
        ckre = fmaf(a, cs, ckre);
        ckim = fmaf(a, sn, ckim);
    }

    int base = row * S4;
#pragma unroll
    for (int k = 0; k < S4 / 256; k++) {
        int i = base + threadIdx.x + k * 256;
        float4 a = __ldcs(&hr[i]);         // consume-once
        float4 b = __ldcs(&hi[i]);
        float4 o0, o1;
        o0.x = a.x * ckre - b.x * ckim;  o1.x = a.x * ckim + b.x * ckre;
        o0.y = a.y * ckre - b.y * ckim;  o1.y = a.y * ckim + b.y * ckre;
        o0.z = a.z * ckre - b.z * ckim;  o1.z = a.z * ckim + b.z * ckre;
        o0.w = a.w * ckre - b.w * ckim;  o1.w = a.w * ckim + b.w * ckre;
        __stcs(&out[i],          o0);      // real plane
        __stcs(&out[i + W * S4], o1);      // imag plane
    }
}

// ---------------- launcher ----------------
extern "C" void kernel_launch(void* const* d_in, const int* in_sizes, int n_in,
                              void* d_out, int out_size) {
    const float4* hr = (const float4*)d_in[0];
    const float4* hi = (const float4*)d_in[1];
    const float4* cr = (const float4*)d_in[2];
    const float4* ci = (const float4*)d_in[3];
    const int*    nk = (const int*)d_in[4];

    k_main<<<W, 256>>>(hr, hi, cr, ci, nk);
    k_out <<<W, 256>>>(hr, hi, (float4*)d_out);
}

// round 7
// speedup vs baseline: 1.9745x; 1.0496x over previous
#include <cuda_runtime.h>
#include <math.h>

#define W 4096
#define S4 1024           // float4 per row
#define NKMAX 1024
#define SHARP 50.0f
#define MAXWIN 64
#define CGRID 256         // corr blocks
#define CK (NKMAX/CGRID)  // keys per corr block (4)

// ---------------- device scratch (no allocations allowed) ----------------
__device__ float2 g_mix[W];       // noisy_mix
__device__ float2 g_tw[W];        // twiddle table e^{i 2pi m / W}
__device__ float  g_corr[NKMAX];
__device__ unsigned g_t2;         // corr block ticket   (monotonic across replays)
__device__ unsigned g_t3;         // out block ticket    (monotonic across replays)
__device__ unsigned g_done;       // softmax completion epoch (monotonic)
__device__ int    g_nwin;         // number of nonzero-attention winners
__device__ int    g_winn[MAXWIN]; // winner key indices (sorted ascending)
__device__ float  g_wina[MAXWIN]; // winner attention weights

// block-wide complex reduction (256 threads, 8 warps). Caller syncs before reuse.
__device__ __forceinline__ float2 block_reduce_c(float re, float im, float2* sred) {
#pragma unroll
    for (int off = 16; off; off >>= 1) {
        re += __shfl_xor_sync(0xffffffffu, re, off);
        im += __shfl_xor_sync(0xffffffffu, im, off);
    }
    int wid = threadIdx.x >> 5;
    if ((threadIdx.x & 31) == 0) sred[wid] = make_float2(re, im);
    __syncthreads();
    float2 acc = sred[0];
#pragma unroll
    for (int i = 1; i < 8; i++) { acc.x += sred[i].x; acc.y += sred[i].y; }
    return acc;
}

// ---------------- phase 1: noisy_mix[w] = sum_s holo*conj(cue) ----------------
__global__ __launch_bounds__(256) void k_mix(
    const float4* __restrict__ hr, const float4* __restrict__ hi,
    const float4* __restrict__ cr, const float4* __restrict__ ci)
{
    int row = blockIdx.x;
    int t   = threadIdx.x;
    if (row < 16) {   // side job: twiddle table
        int i = row * 256 + t;
        float s, c;
        sincospif((float)i * (1.0f / 2048.0f), &s, &c);  // i/2048 exact in fp32
        g_tw[i] = make_float2(c, s);
    }
    int base = row * S4;
    float re = 0.f, im = 0.f;
#pragma unroll
    for (int k = 0; k < 4; k++) {
        int i = base + t + k * 256;
        float4 a = hr[i];            // retain in L2 for k_out
        float4 b = hi[i];
        float4 c = __ldcs(&cr[i]);   // streaming
        float4 d = __ldcs(&ci[i]);
        re += a.x * c.x + b.x * d.x;  im += b.x * c.x - a.x * d.x;
        re += a.y * c.y + b.y * d.y;  im += b.y * c.y - a.y * d.y;
        re += a.z * c.z + b.z * d.z;  im += b.z * c.z - a.z * d.z;
        re += a.w * c.w + b.w * d.w;  im += b.w * c.w - a.w * d.w;
    }
    __shared__ float2 sred[8];
    float2 acc = block_reduce_c(re, im, sred);
    if (t == 0) g_mix[row] = acc;
}

// ------ phase 2: correlations (phasor recurrence) + last-block softmax ------
__global__ __launch_bounds__(256) void k_corr(const int* __restrict__ nkp) {
    cudaTriggerProgrammaticLaunchCompletion();   // release k_out's PDL launch
    cudaGridDependencySynchronize();             // k_mix fully done (no early trigger)

    int t   = threadIdx.x;
    int cid = blockIdx.x;
    int nk  = *nkp;
    __shared__ float2 sred[8];

    // key f: twiddle at w advances by rot = e^{i 2pi f*256/W} per 256-step chunk
    float tre[CK], tim[CK], rre[CK], rim[CK], are[CK], aim[CK];
#pragma unroll
    for (int kk = 0; kk < CK; kk++) {
        unsigned f = (unsigned)(cid * CK + kk) + 1u;
        float2 t0 = g_tw[(f * (unsigned)t) & 4095u];   // exact init
        float2 r0 = g_tw[(f << 8) & 4095u];            // exact rotation const
        tre[kk] = t0.x; tim[kk] = t0.y;
        rre[kk] = r0.x; rim[kk] = r0.y;
        are[kk] = 0.f;  aim[kk] = 0.f;
    }
#pragma unroll
    for (int ch = 0; ch < 16; ch++) {
        float2 m = __ldg(&g_mix[t + 256 * ch]);
#pragma unroll
        for (int kk = 0; kk < CK; kk++) {
            are[kk] += tre[kk] * m.x - tim[kk] * m.y;
            aim[kk] += tre[kk] * m.y + tim[kk] * m.x;
            float nr = tre[kk] * rre[kk] - tim[kk] * rim[kk];
            tim[kk]  = tre[kk] * rim[kk] + tim[kk] * rre[kk];
            tre[kk]  = nr;
        }
    }
#pragma unroll
    for (int kk = 0; kk < CK; kk++) {
        float2 acc = block_reduce_c(are[kk], aim[kk], sred);
        int n = cid * CK + kk;
        if (t == 0 && n < nk) g_corr[n] = sqrtf(acc.x * acc.x + acc.y * acc.y);
        __syncthreads();
    }
    __threadfence();

    // last-arriving block (monotonic ticket) does softmax + winner compaction
    __shared__ unsigned sT2;
    if (t == 0) sT2 = atomicAdd(&g_t2, 1u);
    __syncthreads();
    if ((sT2 & (CGRID - 1u)) != (CGRID - 1u)) return;
    __threadfence();

    __shared__ float sredf[8];
    __shared__ float slog[NKMAX];
    __shared__ int   s_cnt;
    if (t == 0) s_cnt = 0;

    float l[4], mx = -INFINITY;
#pragma unroll
    for (int j = 0; j < 4; j++) {
        int n = t + 256 * j;
        float c = (n < nk) ? __ldcg(&g_corr[n]) : 0.f;
        l[j] = (n < nk) ? c * SHARP : -INFINITY;
        mx = fmaxf(mx, l[j]);
    }
#pragma unroll
    for (int off = 16; off; off >>= 1) mx = fmaxf(mx, __shfl_xor_sync(0xffffffffu, mx, off));
    if ((t & 31) == 0) sredf[t >> 5] = mx;
    __syncthreads();
    float bm = sredf[0];
#pragma unroll
    for (int i = 1; i < 8; i++) bm = fmaxf(bm, sredf[i]);
    __syncthreads();

    float e[4], s = 0.f;
#pragma unroll
    for (int j = 0; j < 4; j++) {
        int n = t + 256 * j;
        e[j] = (n < nk) ? expf(l[j] - bm) : 0.f;
        slog[t + 256 * j] = e[j];
        s += e[j];
    }
#pragma unroll
    for (int off = 16; off; off >>= 1) s += __shfl_xor_sync(0xffffffffu, s, off);
    if ((t & 31) == 0) sredf[t >> 5] = s;
    __syncthreads();
    float bs = sredf[0];
#pragma unroll
    for (int i = 1; i < 8; i++) bs += sredf[i];
    __syncthreads();

#pragma unroll
    for (int j = 0; j < 4; j++) {
        int n = t + 256 * j;
        float a = slog[n] / bs;
        if (a != 0.f && n < nk) {
            int slot = atomicAdd(&s_cnt, 1);
            if (slot < MAXWIN) { g_winn[slot] = n; g_wina[slot] = a; }
        }
    }
    __syncthreads();
    if (t == 0) {
        int m = s_cnt < MAXWIN ? s_cnt : MAXWIN;
        for (int i = 1; i < m; i++) {           // sort ascending by n
            int   kn = g_winn[i];
            float ka = g_wina[i];
            int j = i - 1;
            while (j >= 0 && g_winn[j] > kn) {
                g_winn[j + 1] = g_winn[j]; g_wina[j + 1] = g_wina[j]; j--;
            }
            g_winn[j + 1] = kn; g_wina[j + 1] = ka;
        }
        g_nwin = m;
        __threadfence();
        atomicAdd(&g_done, 1u);                 // publish epoch
    }
}

// ---------------- phase 3: out = holo * clean_key[:,None] ----------------
// PDL-launched concurrently with k_corr: prefetch full row into registers,
// spin on the softmax epoch, then multiply + store.
__global__ __launch_bounds__(256) void k_out(
    const float4* __restrict__ hr, const float4* __restrict__ hi,
    float4* __restrict__ out)
{
    cudaGridDependencySynchronize();            // k_corr has triggered (at entry)

    int t    = threadIdx.x;
    int row  = (W - 1) - blockIdx.x;            // reverse: hit L2-hot tail of k_mix
    int base = row * S4;
    int i0 = base + t, i1 = i0 + 256, i2 = i0 + 512, i3 = i0 + 768;

    // prefetch entire row (overlaps with k_corr's compute under PDL)
    float4 a0 = hr[i0], b0 = hi[i0];
    float4 a1 = hr[i1], b1 = hi[i1];
    float4 a2 = hr[i2], b2 = hi[i2];
    float4 a3 = hr[i3], b3 = hi[i3];

    // replay index (monotonic ticket) + spin for this replay's softmax epoch
    __shared__ unsigned sR;
    if (t == 0) sR = atomicAdd(&g_t3, 1u) >> 12;    // / 4096 blocks per launch
    __syncthreads();
    unsigned rep = sR;
    if (t == 0) {
        volatile unsigned* p = &g_done;
        while (*p <= rep) __nanosleep(128);
    }
    __syncthreads();
    __threadfence();

    // clean_key[row] from compacted winners (one-hot in practice)
    int m = g_nwin;
    const float F = (float)(6.283185307179586 / 4096.0);  // fl(2*pi/W)
    float fw = (float)row;
    float ckre = 0.f, ckim = 0.f;
    for (int i = 0; i < m; i++) {
        int   n = g_winn[i];
        float a = g_wina[i];
        float freq = (float)(n + 1) * F;   // reference rounding order
        float ph   = freq * fw;
        float sn, cs;
        sincosf(ph, &sn, &cs);
        ckre = fmaf(a, cs, ckre);
        ckim = fmaf(a, sn, ckim);
    }

#define EMIT(ai, bi, idx)                                              \
    {                                                                  \
        float4 o0, o1;                                                 \
        o0.x = ai.x * ckre - bi.x * ckim;  o1.x = ai.x * ckim + bi.x * ckre; \
        o0.y = ai.y * ckre - bi.y * ckim;  o1.y = ai.y * ckim + bi.y * ckre; \
        o0.z = ai.z * ckre - bi.z * ckim;  o1.z = ai.z * ckim + bi.z * ckre; \
        o0.w = ai.w * ckre - bi.w * ckim;  o1.w = ai.w * ckim + bi.w * ckre; \
        __stcs(&out[idx],            o0);                              \
        __stcs(&out[idx + W * S4],   o1);                              \
    }
    EMIT(a0, b0, i0)
    EMIT(a1, b1, i1)
    EMIT(a2, b2, i2)
    EMIT(a3, b3, i3)
#undef EMIT
}

// ---------------- launcher ----------------
extern "C" void kernel_launch(void* const* d_in, const int* in_sizes, int n_in,
                              void* d_out, int out_size) {
    const float4* hr = (const float4*)d_in[0];
    const float4* hi = (const float4*)d_in[1];
    const float4* cr = (const float4*)d_in[2];
    const float4* ci = (const float4*)d_in[3];
    const int*    nk = (const int*)d_in[4];

    k_mix<<<W, 256>>>(hr, hi, cr, ci);

    cudaLaunchAttribute at[1];
    at[0].id = cudaLaunchAttributeProgrammaticStreamSerialization;
    at[0].val.programmaticStreamSerializationAllowed = 1;

    cudaLaunchConfig_t c1 = {};
    c1.gridDim  = dim3(CGRID);
    c1.blockDim = dim3(256);
    c1.stream   = 0;
    c1.attrs    = at;
    c1.numAttrs = 1;
    cudaLaunchKernelEx(&c1, k_corr, nk);

    cudaLaunchConfig_t c2 = {};
    c2.gridDim  = dim3(W);
    c2.blockDim = dim3(256);
    c2.stream   = 0;
    c2.attrs    = at;
    c2.numAttrs = 1;
    cudaLaunchKernelEx(&c2, k_out, hr, hi, (float4*)d_out);
}

// round 8
// speedup vs baseline: 1.9752x; 1.0003x over previous
#include <cuda_runtime.h>
#include <math.h>

#define W 4096
#define S4 1024           // float4 per row
#define NKMAX 1024
#define SHARP 50.0f
#define MAXWIN 64
#define CGRID 256         // corr blocks
#define CK (NKMAX/CGRID)  // keys per corr block (4)

// ---------------- device scratch (no allocations allowed) ----------------
__device__ float2 g_mix[W];       // noisy_mix
__device__ float2 g_tw[W];        // twiddle table e^{i 2pi m / W}
__device__ float  g_corr[NKMAX];
__device__ unsigned g_t2;         // corr block ticket   (monotonic across replays)
__device__ unsigned g_t3;         // out block ticket    (monotonic across replays)
__device__ unsigned g_done;       // softmax completion epoch (monotonic)
__device__ int    g_nwin;         // number of nonzero-attention winners
__device__ int    g_winn[MAXWIN]; // winner key indices (sorted ascending)
__device__ float  g_wina[MAXWIN]; // winner attention weights

// block-wide complex reduction (256 threads, 8 warps). Caller syncs before reuse.
__device__ __forceinline__ float2 block_reduce_c(float re, float im, float2* sred) {
#pragma unroll
    for (int off = 16; off; off >>= 1) {
        re += __shfl_xor_sync(0xffffffffu, re, off);
        im += __shfl_xor_sync(0xffffffffu, im, off);
    }
    int wid = threadIdx.x >> 5;
    if ((threadIdx.x & 31) == 0) sred[wid] = make_float2(re, im);
    __syncthreads();
    float2 acc = sred[0];
#pragma unroll
    for (int i = 1; i < 8; i++) { acc.x += sred[i].x; acc.y += sred[i].y; }
    return acc;
}

// ---------------- phase 1: noisy_mix[w] = sum_s holo*conj(cue) ----------------
__global__ __launch_bounds__(256) void k_mix(
    const float4* __restrict__ hr, const float4* __restrict__ hi,
    const float4* __restrict__ cr, const float4* __restrict__ ci)
{
    int row = blockIdx.x;
    int t   = threadIdx.x;
    if (row < 16) {   // side job: twiddle table
        int i = row * 256 + t;
        float s, c;
        sincospif((float)i * (1.0f / 2048.0f), &s, &c);  // i/2048 exact in fp32
        g_tw[i] = make_float2(c, s);
    }
    int base = row * S4;
    float re = 0.f, im = 0.f;
#pragma unroll
    for (int k = 0; k < 4; k++) {
        int i = base + t + k * 256;
        float4 a = hr[i];            // retain in L2 for k_out
        float4 b = hi[i];
        float4 c = __ldcs(&cr[i]);   // streaming
        float4 d = __ldcs(&ci[i]);
        re += a.x * c.x + b.x * d.x;  im += b.x * c.x - a.x * d.x;
        re += a.y * c.y + b.y * d.y;  im += b.y * c.y - a.y * d.y;
        re += a.z * c.z + b.z * d.z;  im += b.z * c.z - a.z * d.z;
        re += a.w * c.w + b.w * d.w;  im += b.w * c.w - a.w * d.w;
    }
    __shared__ float2 sred[8];
    float2 acc = block_reduce_c(re, im, sred);
    if (t == 0) g_mix[row] = acc;
}

// ------ phase 2: correlations (phasor recurrence) + last-block softmax ------
__global__ __launch_bounds__(256) void k_corr(const int* __restrict__ nkp) {
    cudaTriggerProgrammaticLaunchCompletion();   // release k_out's PDL launch
    cudaGridDependencySynchronize();             // k_mix fully done (no early trigger)

    int t   = threadIdx.x;
    int cid = blockIdx.x;
    int nk  = *nkp;
    __shared__ float2 sred[8];

    // key f: twiddle at w advances by rot = e^{i 2pi f*256/W} per 256-step chunk
    float tre[CK], tim[CK], rre[CK], rim[CK], are[CK], aim[CK];
#pragma unroll
    for (int kk = 0; kk < CK; kk++) {
        unsigned f = (unsigned)(cid * CK + kk) + 1u;
        float2 t0 = g_tw[(f * (unsigned)t) & 4095u];   // exact init
        float2 r0 = g_tw[(f << 8) & 4095u];            // exact rotation const
        tre[kk] = t0.x; tim[kk] = t0.y;
        rre[kk] = r0.x; rim[kk] = r0.y;
        are[kk] = 0.f;  aim[kk] = 0.f;
    }
#pragma unroll
    for (int ch = 0; ch < 16; ch++) {
        float2 m = __ldg(&g_mix[t + 256 * ch]);
#pragma unroll
        for (int kk = 0; kk < CK; kk++) {
            are[kk] += tre[kk] * m.x - tim[kk] * m.y;
            aim[kk] += tre[kk] * m.y + tim[kk] * m.x;
            float nr = tre[kk] * rre[kk] - tim[kk] * rim[kk];
            tim[kk]  = tre[kk] * rim[kk] + tim[kk] * rre[kk];
            tre[kk]  = nr;
        }
    }
#pragma unroll
    for (int kk = 0; kk < CK; kk++) {
        float2 acc = block_reduce_c(are[kk], aim[kk], sred);
        int n = cid * CK + kk;
        if (t == 0 && n < nk) g_corr[n] = sqrtf(acc.x * acc.x + acc.y * acc.y);
        __syncthreads();
    }
    __threadfence();

    // last-arriving block (monotonic ticket) does softmax + winner compaction
    __shared__ unsigned sT2;
    if (t == 0) sT2 = atomicAdd(&g_t2, 1u);
    __syncthreads();
    if ((sT2 & (CGRID - 1u)) != (CGRID - 1u)) return;
    __threadfence();

    __shared__ float sredf[8];
    __shared__ float slog[NKMAX];
    __shared__ int   s_cnt;
    if (t == 0) s_cnt = 0;

    float l[4], mx = -INFINITY;
#pragma unroll
    for (int j = 0; j < 4; j++) {
        int n = t + 256 * j;
        float c = (n < nk) ? __ldcg(&g_corr[n]) : 0.f;
        l[j] = (n < nk) ? c * SHARP : -INFINITY;
        mx = fmaxf(mx, l[j]);
    }
#pragma unroll
    for (int off = 16; off; off >>= 1) mx = fmaxf(mx, __shfl_xor_sync(0xffffffffu, mx, off));
    if ((t & 31) == 0) sredf[t >> 5] = mx;
    __syncthreads();
    float bm = sredf[0];
#pragma unroll
    for (int i = 1; i < 8; i++) bm = fmaxf(bm, sredf[i]);
    __syncthreads();

    float e[4], s = 0.f;
#pragma unroll
    for (int j = 0; j < 4; j++) {
        int n = t + 256 * j;
        e[j] = (n < nk) ? expf(l[j] - bm) : 0.f;
        slog[t + 256 * j] = e[j];
        s += e[j];
    }
#pragma unroll
    for (int off = 16; off; off >>= 1) s += __shfl_xor_sync(0xffffffffu, s, off);
    if ((t & 31) == 0) sredf[t >> 5] = s;
    __syncthreads();
    float bs = sredf[0];
#pragma unroll
    for (int i = 1; i < 8; i++) bs += sredf[i];
    __syncthreads();

#pragma unroll
    for (int j = 0; j < 4; j++) {
        int n = t + 256 * j;
        float a = slog[n] / bs;
        if (a != 0.f && n < nk) {
            int slot = atomicAdd(&s_cnt, 1);
            if (slot < MAXWIN) { g_winn[slot] = n; g_wina[slot] = a; }
        }
    }
    __syncthreads();
    if (t == 0) {
        int m = s_cnt < MAXWIN ? s_cnt : MAXWIN;
        for (int i = 1; i < m; i++) {           // sort ascending by n
            int   kn = g_winn[i];
            float ka = g_wina[i];
            int j = i - 1;
            while (j >= 0 && g_winn[j] > kn) {
                g_winn[j + 1] = g_winn[j]; g_wina[j + 1] = g_wina[j]; j--;
            }
            g_winn[j + 1] = kn; g_wina[j + 1] = ka;
        }
        g_nwin = m;
        __threadfence();
        atomicAdd(&g_done, 1u);                 // publish epoch
    }
}

// ---------------- phase 3: out = holo * clean_key[:,None] ----------------
// PDL-launched concurrently with k_corr: prefetch full row into registers,
// spin on the softmax epoch, then multiply + store.
__global__ __launch_bounds__(256) void k_out(
    const float4* __restrict__ hr, const float4* __restrict__ hi,
    float4* __restrict__ out)
{
    cudaGridDependencySynchronize();            // k_corr has triggered (at entry)

    int t    = threadIdx.x;
    int row  = (W - 1) - blockIdx.x;            // reverse: hit L2-hot tail of k_mix
    int base = row * S4;
    int i0 = base + t, i1 = i0 + 256, i2 = i0 + 512, i3 = i0 + 768;

    // prefetch entire row (overlaps with k_corr's compute under PDL)
    float4 a0 = hr[i0], b0 = hi[i0];
    float4 a1 = hr[i1], b1 = hi[i1];
    float4 a2 = hr[i2], b2 = hi[i2];
    float4 a3 = hr[i3], b3 = hi[i3];

    // replay index (monotonic ticket) + spin for this replay's softmax epoch
    __shared__ unsigned sR;
    if (t == 0) sR = atomicAdd(&g_t3, 1u) >> 12;    // / 4096 blocks per launch
    __syncthreads();
    unsigned rep = sR;
    if (t == 0) {
        volatile unsigned* p = &g_done;
        while (*p <= rep) __nanosleep(128);
    }
    __syncthreads();
    __threadfence();

    // clean_key[row] from compacted winners (one-hot in practice)
    int m = g_nwin;
    const float F = (float)(6.283185307179586 / 4096.0);  // fl(2*pi/W)
    float fw = (float)row;
    float ckre = 0.f, ckim = 0.f;
    for (int i = 0; i < m; i++) {
        int   n = g_winn[i];
        float a = g_wina[i];
        float freq = (float)(n + 1) * F;   // reference rounding order
        float ph   = freq * fw;
        float sn, cs;
        sincosf(ph, &sn, &cs);
        ckre = fmaf(a, cs, ckre);
        ckim = fmaf(a, sn, ckim);
    }

#define EMIT(ai, bi, idx)                                              \
    {                                                                  \
        float4 o0, o1;                                                 \
        o0.x = ai.x * ckre - bi.x * ckim;  o1.x = ai.x * ckim + bi.x * ckre; \
        o0.y = ai.y * ckre - bi.y * ckim;  o1.y = ai.y * ckim + bi.y * ckre; \
        o0.z = ai.z * ckre - bi.z * ckim;  o1.z = ai.z * ckim + bi.z * ckre; \
        o0.w = ai.w * ckre - bi.w * ckim;  o1.w = ai.w * ckim + bi.w * ckre; \
        __stcs(&out[idx],            o0);                              \
        __stcs(&out[idx + W * S4],   o1);                              \
    }
    EMIT(a0, b0, i0)
    EMIT(a1, b1, i1)
    EMIT(a2, b2, i2)
    EMIT(a3, b3, i3)
#undef EMIT
}

// ---------------- launcher ----------------
extern "C" void kernel_launch(void* const* d_in, const int* in_sizes, int n_in,
                              void* d_out, int out_size) {
    const float4* hr = (const float4*)d_in[0];
    const float4* hi = (const float4*)d_in[1];
    const float4* cr = (const float4*)d_in[2];
    const float4* ci = (const float4*)d_in[3];
    const int*    nk = (const int*)d_in[4];

    k_mix<<<W, 256>>>(hr, hi, cr, ci);

    cudaLaunchAttribute at[1];
    at[0].id = cudaLaunchAttributeProgrammaticStreamSerialization;
    at[0].val.programmaticStreamSerializationAllowed = 1;

    cudaLaunchConfig_t c1 = {};
    c1.gridDim  = dim3(CGRID);
    c1.blockDim = dim3(256);
    c1.stream   = 0;
    c1.attrs    = at;
    c1.numAttrs = 1;
    cudaLaunchKernelEx(&c1, k_corr, nk);

    cudaLaunchConfig_t c2 = {};
    c2.gridDim  = dim3(W);
    c2.blockDim = dim3(256);
    c2.stream   = 0;
    c2.attrs    = at;
    c2.numAttrs = 1;
    cudaLaunchKernelEx(&c2, k_out, hr, hi, (float4*)d_out);
}